// round 1
// baseline (speedup 1.0000x reference)
#include <cuda_runtime.h>
#include <cstdint>

// ---------------- problem constants ----------------
#define CCH   200               // channels
#define NC4   50                // CCH/4 float4 chunks
#define D3    16
#define H3    60
#define W3    80
#define P3    (D3*H3*W3)        // 76800 positions per batch (3D)
#define H2    120
#define W2    160
#define P2    (H2*W2)           // 19200 positions per batch (2D)
#define XDIM  60
#define YDIM  36
#define ZDIM  60
#define NVOX  (XDIM*YDIM*ZDIM)  // 129600
#define NB    2

// channel-last scratch: s3[b][pos][c], s2[b][pos][c]
__device__ float g_s3[NB * P3 * CCH];   // 122.88 MB
__device__ float g_s2[NB * P2 * CCH];   //  30.72 MB

// ---------------- pass 1: add + transpose (C,P) -> (P,C) ----------------
// in:  a,b  [batch][C][P]   out: dst [batch][P][C]
__global__ void transpose_add_kernel(const float* __restrict__ a,
                                     const float* __restrict__ b,
                                     float* __restrict__ dst,
                                     int P)
{
    __shared__ float tile[32][33];
    const int pt = blockIdx.x;          // p tile
    const int ct = blockIdx.y;          // c tile (7 tiles for C=200)
    const int batch = blockIdx.z;
    const float* ab = a + (size_t)batch * CCH * P;
    const float* bb = b + (size_t)batch * CCH * P;
    float* db = dst + (size_t)batch * P * CCH;

    const int p0 = pt * 32, c0 = ct * 32;
    const int tx = threadIdx.x, ty = threadIdx.y;   // 32 x 8

    #pragma unroll
    for (int i = 0; i < 32; i += 8) {
        int c = c0 + ty + i;
        int p = p0 + tx;                // P divisible by 32, no bound check
        if (c < CCH)
            tile[ty + i][tx] = ab[(size_t)c * P + p] + bb[(size_t)c * P + p];
    }
    __syncthreads();
    #pragma unroll
    for (int i = 0; i < 32; i += 8) {
        int p = p0 + ty + i;
        int c = c0 + tx;
        if (c < CCH)
            db[(size_t)p * CCH + c] = tile[tx][ty + i];
    }
}

// ---------------- pass 2: warp-per-voxel gather ----------------
// block = 256 threads = 8 warps = 8 consecutive z of one (b,x,y) column
__global__ void __launch_bounds__(256) sample_kernel(const float* __restrict__ pp,
                                                     float* __restrict__ out)
{
    const int bid  = blockIdx.x;
    const int zc   = bid & 7;           // z chunk (8 per column)
    int rest       = bid >> 3;
    const int y    = rest % YDIM; rest /= YDIM;
    const int x    = rest % XDIM;
    const int b    = rest / XDIM;

    const int warp = threadIdx.x >> 5;
    const int lane = threadIdx.x & 31;
    const int z    = zc * 8 + warp;
    if (z >= ZDIM) return;

    // voxel index in projected_pix order: v = x*(Z*Y) + z*Y + y
    const int v = x * (ZDIM * YDIM) + z * YDIM + y;
    const float* g = pp + ((size_t)b * NVOX + v) * 3;
    const float px = g[0], py = g[1], pz = g[2];

    // ---- 3D taps (W3=80, H3=60, D3=16) ----
    const float gx3 = (px + 1.f) * 0.5f * (W3 - 1);
    const float gy3 = (py + 1.f) * 0.5f * (H3 - 1);
    const float gz3 = (pz + 1.f) * 0.5f * (D3 - 1);
    const float fx3 = floorf(gx3), fy3 = floorf(gy3), fz3 = floorf(gz3);
    const int ix3 = (int)fx3, iy3 = (int)fy3, iz3 = (int)fz3;
    const float wx3 = gx3 - fx3, wy3 = gy3 - fy3, wz3 = gz3 - fz3;

    int   off3[8];
    float w3[8];
    #pragma unroll
    for (int t = 0; t < 8; t++) {
        const int dx = t & 1, dy = (t >> 1) & 1, dz = (t >> 2) & 1;
        const int xi = ix3 + dx, yi = iy3 + dy, zi = iz3 + dz;
        const bool valid = (xi >= 0) & (xi < W3) & (yi >= 0) & (yi < H3) &
                           (zi >= 0) & (zi < D3);
        const int xcl = min(max(xi, 0), W3 - 1);
        const int ycl = min(max(yi, 0), H3 - 1);
        const int zcl = min(max(zi, 0), D3 - 1);
        off3[t] = (zcl * H3 + ycl) * W3 + xcl;
        float w = (dx ? wx3 : 1.f - wx3) * (dy ? wy3 : 1.f - wy3) *
                  (dz ? wz3 : 1.f - wz3);
        w3[t] = valid ? w : 0.f;
    }

    // ---- 2D taps (W2=160, H2=120) ----
    const float gx2 = (px + 1.f) * 0.5f * (W2 - 1);
    const float gy2 = (py + 1.f) * 0.5f * (H2 - 1);
    const float fx2 = floorf(gx2), fy2 = floorf(gy2);
    const int ix2 = (int)fx2, iy2 = (int)fy2;
    const float wx2 = gx2 - fx2, wy2 = gy2 - fy2;

    int   off2[4];
    float w2[4];
    #pragma unroll
    for (int t = 0; t < 4; t++) {
        const int dx = t & 1, dy = (t >> 1) & 1;
        const int xi = ix2 + dx, yi = iy2 + dy;
        const bool valid = (xi >= 0) & (xi < W2) & (yi >= 0) & (yi < H2);
        const int xcl = min(max(xi, 0), W2 - 1);
        const int ycl = min(max(yi, 0), H2 - 1);
        off2[t] = ycl * W2 + xcl;
        float w = (dx ? wx2 : 1.f - wx2) * (dy ? wy2 : 1.f - wy2);
        w2[t] = valid ? w : 0.f;
    }

    // ---- channel accumulation (float4, coalesced across lanes) ----
    const float4* s3 = (const float4*)g_s3 + (size_t)b * P3 * NC4;
    const float4* s2 = (const float4*)g_s2 + (size_t)b * P2 * NC4;
    // out[b][c][x][y][z]
    float* ob = out + (size_t)b * CCH * NVOX +
                ((size_t)x * YDIM + y) * ZDIM + z;

    for (int cc = lane; cc < NC4; cc += 32) {
        float4 acc = make_float4(0.f, 0.f, 0.f, 0.f);
        #pragma unroll
        for (int t = 0; t < 8; t++) {
            const float4 val = s3[(size_t)off3[t] * NC4 + cc];
            acc.x += w3[t] * val.x;
            acc.y += w3[t] * val.y;
            acc.z += w3[t] * val.z;
            acc.w += w3[t] * val.w;
        }
        #pragma unroll
        for (int t = 0; t < 4; t++) {
            const float4 val = s2[(size_t)off2[t] * NC4 + cc];
            acc.x += w2[t] * val.x;
            acc.y += w2[t] * val.y;
            acc.z += w2[t] * val.z;
            acc.w += w2[t] * val.w;
        }
        float* o = ob + (size_t)(cc * 4) * NVOX;
        o[0 * (size_t)NVOX] = acc.x;
        o[1 * (size_t)NVOX] = acc.y;
        o[2 * (size_t)NVOX] = acc.z;
        o[3 * (size_t)NVOX] = acc.w;
    }
}

// ---------------- launch ----------------
extern "C" void kernel_launch(void* const* d_in, const int* in_sizes, int n_in,
                              void* d_out, int out_size)
{
    const float* x3a = (const float*)d_in[0];
    const float* x3b = (const float*)d_in[1];
    const float* x2a = (const float*)d_in[2];
    const float* x2b = (const float*)d_in[3];
    const float* pp  = (const float*)d_in[4];
    float* out = (float*)d_out;

    float* s3ptr = nullptr;
    float* s2ptr = nullptr;
    cudaGetSymbolAddress((void**)&s3ptr, g_s3);
    cudaGetSymbolAddress((void**)&s2ptr, g_s2);

    // pass 1: fold + transpose to channel-last
    {
        dim3 blk(32, 8);
        dim3 g3(P3 / 32, (CCH + 31) / 32, NB);   // 2400 x 7 x 2
        transpose_add_kernel<<<g3, blk>>>(x3a, x3b, s3ptr, P3);
        dim3 g2(P2 / 32, (CCH + 31) / 32, NB);   // 600 x 7 x 2
        transpose_add_kernel<<<g2, blk>>>(x2a, x2b, s2ptr, P2);
    }

    // pass 2: warp-per-voxel sampling
    {
        const int nblocks = NB * XDIM * YDIM * 8;  // 34560
        sample_kernel<<<nblocks, 256>>>(pp, out);
    }
}

// round 2
// speedup vs baseline: 1.6091x; 1.6091x over previous
#include <cuda_runtime.h>
#include <cstdint>

// ---------------- problem constants ----------------
#define CCH   200               // channels
#define NC4   50                // CCH/4 float4 chunks
#define D3    16
#define H3    60
#define W3    80
#define P3    (D3*H3*W3)        // 76800 positions per batch (3D)
#define H2    120
#define W2    160
#define P2    (H2*W2)           // 19200 positions per batch (2D)
#define XDIM  60
#define YDIM  36
#define ZDIM  60
#define NVOX  (XDIM*YDIM*ZDIM)  // 129600
#define NB    2

// channel-last scratch: s3[b][pos][c], s2[b][pos][c]
__device__ float g_s3[NB * P3 * CCH];   // 122.88 MB
__device__ float g_s2[NB * P2 * CCH];   //  30.72 MB

// ---------------- pass 1: add + transpose (C,P) -> (P,C) ----------------
__global__ void transpose_add_kernel(const float* __restrict__ a,
                                     const float* __restrict__ b,
                                     float* __restrict__ dst,
                                     int P)
{
    __shared__ float tile[32][33];
    const int pt = blockIdx.x;
    const int ct = blockIdx.y;
    const int batch = blockIdx.z;
    const float* ab = a + (size_t)batch * CCH * P;
    const float* bb = b + (size_t)batch * CCH * P;
    float* db = dst + (size_t)batch * P * CCH;

    const int p0 = pt * 32, c0 = ct * 32;
    const int tx = threadIdx.x, ty = threadIdx.y;   // 32 x 8

    #pragma unroll
    for (int i = 0; i < 32; i += 8) {
        int c = c0 + ty + i;
        int p = p0 + tx;
        if (c < CCH)
            tile[ty + i][tx] = ab[(size_t)c * P + p] + bb[(size_t)c * P + p];
    }
    __syncthreads();
    #pragma unroll
    for (int i = 0; i < 32; i += 8) {
        int p = p0 + ty + i;
        int c = c0 + tx;
        if (c < CCH)
            db[(size_t)p * CCH + c] = tile[tx][ty + i];
    }
}

// ---------------- pass 2: warp-per-voxel gather, smem-staged coalesced stores ----
// block = 256 threads = 8 warps = 8 consecutive z of one (b,x,y) column
__global__ void __launch_bounds__(256) sample_kernel(const float* __restrict__ pp,
                                                     float* __restrict__ out)
{
    // row stride 204: conflict-free transposed readout, rows 16B-aligned (816B)
    __shared__ float sm[8][204];

    const int bid  = blockIdx.x;
    const int zc   = bid & 7;           // z chunk (8 per column)
    int rest       = bid >> 3;
    const int y    = rest % YDIM; rest /= YDIM;
    const int x    = rest % XDIM;
    const int b    = rest / XDIM;

    const int warp = threadIdx.x >> 5;
    const int lane = threadIdx.x & 31;
    const int z    = zc * 8 + warp;

    if (z < ZDIM) {
        // voxel index in projected_pix order: v = x*(Z*Y) + z*Y + y
        const int v = x * (ZDIM * YDIM) + z * YDIM + y;
        const float* g = pp + ((size_t)b * NVOX + v) * 3;
        const float px = g[0], py = g[1], pz = g[2];

        // ---- 3D taps ----
        const float gx3 = (px + 1.f) * 0.5f * (W3 - 1);
        const float gy3 = (py + 1.f) * 0.5f * (H3 - 1);
        const float gz3 = (pz + 1.f) * 0.5f * (D3 - 1);
        const float fx3 = floorf(gx3), fy3 = floorf(gy3), fz3 = floorf(gz3);
        const int ix3 = (int)fx3, iy3 = (int)fy3, iz3 = (int)fz3;
        const float wx3 = gx3 - fx3, wy3 = gy3 - fy3, wz3 = gz3 - fz3;

        int   off3[8];
        float w3[8];
        #pragma unroll
        for (int t = 0; t < 8; t++) {
            const int dx = t & 1, dy = (t >> 1) & 1, dz = (t >> 2) & 1;
            const int xi = ix3 + dx, yi = iy3 + dy, zi = iz3 + dz;
            const bool valid = (xi >= 0) & (xi < W3) & (yi >= 0) & (yi < H3) &
                               (zi >= 0) & (zi < D3);
            const int xcl = min(max(xi, 0), W3 - 1);
            const int ycl = min(max(yi, 0), H3 - 1);
            const int zcl = min(max(zi, 0), D3 - 1);
            off3[t] = (zcl * H3 + ycl) * W3 + xcl;
            float w = (dx ? wx3 : 1.f - wx3) * (dy ? wy3 : 1.f - wy3) *
                      (dz ? wz3 : 1.f - wz3);
            w3[t] = valid ? w : 0.f;
        }

        // ---- 2D taps ----
        const float gx2 = (px + 1.f) * 0.5f * (W2 - 1);
        const float gy2 = (py + 1.f) * 0.5f * (H2 - 1);
        const float fx2 = floorf(gx2), fy2 = floorf(gy2);
        const int ix2 = (int)fx2, iy2 = (int)fy2;
        const float wx2 = gx2 - fx2, wy2 = gy2 - fy2;

        int   off2[4];
        float w2[4];
        #pragma unroll
        for (int t = 0; t < 4; t++) {
            const int dx = t & 1, dy = (t >> 1) & 1;
            const int xi = ix2 + dx, yi = iy2 + dy;
            const bool valid = (xi >= 0) & (xi < W2) & (yi >= 0) & (yi < H2);
            const int xcl = min(max(xi, 0), W2 - 1);
            const int ycl = min(max(yi, 0), H2 - 1);
            off2[t] = ycl * W2 + xcl;
            float w = (dx ? wx2 : 1.f - wx2) * (dy ? wy2 : 1.f - wy2);
            w2[t] = valid ? w : 0.f;
        }

        // ---- channel accumulation (float4, coalesced across lanes) ----
        const float4* s3 = (const float4*)g_s3 + (size_t)b * P3 * NC4;
        const float4* s2 = (const float4*)g_s2 + (size_t)b * P2 * NC4;

        for (int cc = lane; cc < NC4; cc += 32) {
            float4 acc = make_float4(0.f, 0.f, 0.f, 0.f);
            #pragma unroll
            for (int t = 0; t < 8; t++) {
                const float4 val = s3[(size_t)off3[t] * NC4 + cc];
                acc.x += w3[t] * val.x;
                acc.y += w3[t] * val.y;
                acc.z += w3[t] * val.z;
                acc.w += w3[t] * val.w;
            }
            #pragma unroll
            for (int t = 0; t < 4; t++) {
                const float4 val = s2[(size_t)off2[t] * NC4 + cc];
                acc.x += w2[t] * val.x;
                acc.y += w2[t] * val.y;
                acc.z += w2[t] * val.z;
                acc.w += w2[t] * val.w;
            }
            *(float4*)&sm[warp][cc * 4] = acc;   // staged in smem
        }
    }
    __syncthreads();

    // ---- cooperative coalesced write-out: out[b][c][x][y][z] ----
    const int z0 = zc * 8;
    float* ob = out + (size_t)b * CCH * NVOX +
                ((size_t)x * YDIM + y) * ZDIM + z0;
    // 800 float2 items: c = idx>>2, z-pair = idx&3. Warp span: 8 c x 4 zp ->
    // 8 full 32B sectors. 8B alignment holds (column base and z0 are even).
    #pragma unroll
    for (int idx = threadIdx.x; idx < CCH * 4; idx += 256) {
        const int c  = idx >> 2;
        const int zp = idx & 3;
        if (z0 + 2 * zp < ZDIM) {
            float2 v = make_float2(sm[2 * zp][c], sm[2 * zp + 1][c]);
            *(float2*)(ob + (size_t)c * NVOX + 2 * zp) = v;
        }
    }
}

// ---------------- launch ----------------
extern "C" void kernel_launch(void* const* d_in, const int* in_sizes, int n_in,
                              void* d_out, int out_size)
{
    const float* x3a = (const float*)d_in[0];
    const float* x3b = (const float*)d_in[1];
    const float* x2a = (const float*)d_in[2];
    const float* x2b = (const float*)d_in[3];
    const float* pp  = (const float*)d_in[4];
    float* out = (float*)d_out;

    float* s3ptr = nullptr;
    float* s2ptr = nullptr;
    cudaGetSymbolAddress((void**)&s3ptr, g_s3);
    cudaGetSymbolAddress((void**)&s2ptr, g_s2);

    // pass 1: fold + transpose to channel-last
    {
        dim3 blk(32, 8);
        dim3 g3(P3 / 32, (CCH + 31) / 32, NB);   // 2400 x 7 x 2
        transpose_add_kernel<<<g3, blk>>>(x3a, x3b, s3ptr, P3);
        dim3 g2(P2 / 32, (CCH + 31) / 32, NB);   // 600 x 7 x 2
        transpose_add_kernel<<<g2, blk>>>(x2a, x2b, s2ptr, P2);
    }

    // pass 2: warp-per-voxel sampling with staged coalesced stores
    {
        const int nblocks = NB * XDIM * YDIM * 8;  // 34560
        sample_kernel<<<nblocks, 256>>>(pp, out);
    }
}

// round 4
// speedup vs baseline: 2.1241x; 1.3200x over previous
#include <cuda_runtime.h>
#include <cuda_fp16.h>
#include <cstdint>

// ---------------- problem constants ----------------
#define CCH   200               // channels
#define NC8   25                // CCH/8 half8 (uint4) chunks
#define D3    16
#define H3    60
#define W3    80
#define P3    (D3*H3*W3)        // 76800 positions per batch (3D)
#define H2    120
#define W2    160
#define P2    (H2*W2)           // 19200 positions per batch (2D)
#define XDIM  60
#define YDIM  36
#define ZDIM  60
#define NVOX  (XDIM*YDIM*ZDIM)  // 129600
#define NB    2

// channel-last fp16 scratch: s3[b][pos][c], s2[b][pos][c]
__device__ __align__(16) __half g_s3[NB * P3 * CCH];   // 61.4 MB
__device__ __align__(16) __half g_s2[NB * P2 * CCH];   // 15.4 MB

// ---------------- pass 1: add + transpose (C,P) -> (P,C), fp32->fp16 ------
__global__ void transpose_add_kernel(const float* __restrict__ a,
                                     const float* __restrict__ b,
                                     __half* __restrict__ dst,
                                     int P)
{
    __shared__ float tile[32][33];   // [c_local][p_local]
    const int pt = blockIdx.x;
    const int ct = blockIdx.y;
    const int batch = blockIdx.z;
    const float* ab = a + (size_t)batch * CCH * P;
    const float* bb = b + (size_t)batch * CCH * P;
    __half* db = dst + (size_t)batch * P * CCH;

    const int p0 = pt * 32, c0 = ct * 32;
    const int tx = threadIdx.x, ty = threadIdx.y;   // 32 x 8

    #pragma unroll
    for (int i = 0; i < 32; i += 8) {
        int c = c0 + ty + i;
        int p = p0 + tx;
        if (c < CCH)
            tile[ty + i][tx] = ab[(size_t)c * P + p] + bb[(size_t)c * P + p];
    }
    __syncthreads();
    #pragma unroll
    for (int i = 0; i < 32; i += 8) {
        int p = p0 + ty + i;
        int c = c0 + tx;
        if (c < CCH)
            db[(size_t)p * CCH + c] = __float2half_rn(tile[tx][ty + i]);
    }
}

// ---------------- pass 2: warp-per-voxel gather (fp16 taps, fp32 accum) ----
// block = 256 threads = 8 warps = 8 consecutive z of one (b,x,y) column
__global__ void __launch_bounds__(256) sample_kernel(const float* __restrict__ pp,
                                                     float* __restrict__ out)
{
    // row stride 204: rows 16B-aligned, readout conflict-light
    __shared__ float sm[8][204];

    const int bid  = blockIdx.x;
    const int zc   = bid & 7;           // z chunk (8 per column)
    int rest       = bid >> 3;
    const int y    = rest % YDIM; rest /= YDIM;
    const int x    = rest % XDIM;
    const int b    = rest / XDIM;

    const int warp = threadIdx.x >> 5;
    const int lane = threadIdx.x & 31;
    const int z    = zc * 8 + warp;

    if (z < ZDIM) {
        // voxel index in projected_pix order: v = x*(Z*Y) + z*Y + y
        const int v = x * (ZDIM * YDIM) + z * YDIM + y;
        const float* g = pp + ((size_t)b * NVOX + v) * 3;
        const float px = g[0], py = g[1], pz = g[2];

        // ---- 3D taps ----
        const float gx3 = (px + 1.f) * 0.5f * (W3 - 1);
        const float gy3 = (py + 1.f) * 0.5f * (H3 - 1);
        const float gz3 = (pz + 1.f) * 0.5f * (D3 - 1);
        const float fx3 = floorf(gx3), fy3 = floorf(gy3), fz3 = floorf(gz3);
        const int ix3 = (int)fx3, iy3 = (int)fy3, iz3 = (int)fz3;
        const float wx3 = gx3 - fx3, wy3 = gy3 - fy3, wz3 = gz3 - fz3;

        int   off3[8];
        float w3[8];
        #pragma unroll
        for (int t = 0; t < 8; t++) {
            const int dx = t & 1, dy = (t >> 1) & 1, dz = (t >> 2) & 1;
            const int xi = ix3 + dx, yi = iy3 + dy, zi = iz3 + dz;
            const bool valid = (xi >= 0) & (xi < W3) & (yi >= 0) & (yi < H3) &
                               (zi >= 0) & (zi < D3);
            const int xcl = min(max(xi, 0), W3 - 1);
            const int ycl = min(max(yi, 0), H3 - 1);
            const int zcl = min(max(zi, 0), D3 - 1);
            off3[t] = (zcl * H3 + ycl) * W3 + xcl;
            float w = (dx ? wx3 : 1.f - wx3) * (dy ? wy3 : 1.f - wy3) *
                      (dz ? wz3 : 1.f - wz3);
            w3[t] = valid ? w : 0.f;
        }

        // ---- 2D taps ----
        const float gx2 = (px + 1.f) * 0.5f * (W2 - 1);
        const float gy2 = (py + 1.f) * 0.5f * (H2 - 1);
        const float fx2 = floorf(gx2), fy2 = floorf(gy2);
        const int ix2 = (int)fx2, iy2 = (int)fy2;
        const float wx2 = gx2 - fx2, wy2 = gy2 - fy2;

        int   off2[4];
        float w2[4];
        #pragma unroll
        for (int t = 0; t < 4; t++) {
            const int dx = t & 1, dy = (t >> 1) & 1;
            const int xi = ix2 + dx, yi = iy2 + dy;
            const bool valid = (xi >= 0) & (xi < W2) & (yi >= 0) & (yi < H2);
            const int xcl = min(max(xi, 0), W2 - 1);
            const int ycl = min(max(yi, 0), H2 - 1);
            off2[t] = ycl * W2 + xcl;
            float w = (dx ? wx2 : 1.f - wx2) * (dy ? wy2 : 1.f - wy2);
            w2[t] = valid ? w : 0.f;
        }

        // ---- channel accumulation: half8 (uint4) loads, fp32 accum ----
        const uint4* s3 = (const uint4*)g_s3 + (size_t)b * P3 * NC8;
        const uint4* s2 = (const uint4*)g_s2 + (size_t)b * P2 * NC8;

        const int cc = lane;            // 0..24 active
        if (cc < NC8) {
            float ax = 0.f, ay = 0.f, az = 0.f, aw = 0.f;
            float bx = 0.f, by = 0.f, bz = 0.f, bw = 0.f;
            #pragma unroll
            for (int t = 0; t < 8; t++) {
                const uint4 vv = s3[(size_t)off3[t] * NC8 + cc];
                const __half2* h = (const __half2*)&vv;
                const float2 f0 = __half22float2(h[0]);
                const float2 f1 = __half22float2(h[1]);
                const float2 f2 = __half22float2(h[2]);
                const float2 f3 = __half22float2(h[3]);
                const float w = w3[t];
                ax += w * f0.x; ay += w * f0.y;
                az += w * f1.x; aw += w * f1.y;
                bx += w * f2.x; by += w * f2.y;
                bz += w * f3.x; bw += w * f3.y;
            }
            #pragma unroll
            for (int t = 0; t < 4; t++) {
                const uint4 vv = s2[(size_t)off2[t] * NC8 + cc];
                const __half2* h = (const __half2*)&vv;
                const float2 f0 = __half22float2(h[0]);
                const float2 f1 = __half22float2(h[1]);
                const float2 f2 = __half22float2(h[2]);
                const float2 f3 = __half22float2(h[3]);
                const float w = w2[t];
                ax += w * f0.x; ay += w * f0.y;
                az += w * f1.x; aw += w * f1.y;
                bx += w * f2.x; by += w * f2.y;
                bz += w * f3.x; bw += w * f3.y;
            }
            *(float4*)&sm[warp][cc * 8]     = make_float4(ax, ay, az, aw);
            *(float4*)&sm[warp][cc * 8 + 4] = make_float4(bx, by, bz, bw);
        }
    }
    __syncthreads();

    // ---- cooperative coalesced write-out: out[b][c][x][y][z] ----
    const int z0 = zc * 8;
    float* ob = out + (size_t)b * CCH * NVOX +
                ((size_t)x * YDIM + y) * ZDIM + z0;
    #pragma unroll
    for (int idx = threadIdx.x; idx < CCH * 4; idx += 256) {
        const int c  = idx >> 2;
        const int zp = idx & 3;
        if (z0 + 2 * zp < ZDIM) {
            float2 v = make_float2(sm[2 * zp][c], sm[2 * zp + 1][c]);
            *(float2*)(ob + (size_t)c * NVOX + 2 * zp) = v;
        }
    }
}

// ---------------- launch ----------------
extern "C" void kernel_launch(void* const* d_in, const int* in_sizes, int n_in,
                              void* d_out, int out_size)
{
    const float* x3a = (const float*)d_in[0];
    const float* x3b = (const float*)d_in[1];
    const float* x2a = (const float*)d_in[2];
    const float* x2b = (const float*)d_in[3];
    const float* pp  = (const float*)d_in[4];
    float* out = (float*)d_out;

    __half* s3ptr = nullptr;
    __half* s2ptr = nullptr;
    cudaGetSymbolAddress((void**)&s3ptr, g_s3);
    cudaGetSymbolAddress((void**)&s2ptr, g_s2);

    // pass 1: fold + transpose to channel-last fp16
    {
        dim3 blk(32, 8);
        dim3 g3(P3 / 32, (CCH + 31) / 32, NB);   // 2400 x 7 x 2
        transpose_add_kernel<<<g3, blk>>>(x3a, x3b, s3ptr, P3);
        dim3 g2(P2 / 32, (CCH + 31) / 32, NB);   // 600 x 7 x 2
        transpose_add_kernel<<<g2, blk>>>(x2a, x2b, s2ptr, P2);
    }

    // pass 2: warp-per-voxel sampling with staged coalesced stores
    {
        const int nblocks = NB * XDIM * YDIM * 8;  // 34560
        sample_kernel<<<nblocks, 256>>>(pp, out);
    }
}

// round 5
// speedup vs baseline: 2.1552x; 1.0146x over previous
#include <cuda_runtime.h>
#include <cuda_fp16.h>
#include <cstdint>

// ---------------- problem constants ----------------
#define CCH   200               // channels
#define NC8   25                // CCH/8 half8 (uint4) chunks
#define D3    16
#define H3    60
#define W3    80
#define P3    (D3*H3*W3)        // 76800 positions per batch (3D)
#define H2    120
#define W2    160
#define P2    (H2*W2)           // 19200 positions per batch (2D)
#define XDIM  60
#define YDIM  36
#define ZDIM  60
#define NVOX  (XDIM*YDIM*ZDIM)  // 129600
#define NB    2

#define T3TILES (P3/32)         // 2400
#define T2TILES (P2/32)         // 600

// channel-last fp16 scratch: s3[b][pos][c], s2[b][pos][c]
__device__ __align__(16) __half g_s3[NB * P3 * CCH];   // 61.4 MB
__device__ __align__(16) __half g_s2[NB * P2 * CCH];   // 15.4 MB

// ---------------- pass 1: fused add + transpose (C,P)->(P,C), fp32->fp16 ---
// blockIdx.x flat: [0,2400) -> 3D tile, [2400,3000) -> 2D tile
__global__ void transpose_add_kernel(const float* __restrict__ a3,
                                     const float* __restrict__ b3,
                                     const float* __restrict__ a2,
                                     const float* __restrict__ b2,
                                     __half* __restrict__ d3,
                                     __half* __restrict__ d2)
{
    __shared__ float tile[32][33];   // [c_local][p_local]
    int pt = blockIdx.x;
    const int ct = blockIdx.y;
    const int batch = blockIdx.z;

    const float *ab, *bb;
    __half* db;
    int P;
    if (pt < T3TILES) {
        P  = P3;
        ab = a3 + (size_t)batch * CCH * P3;
        bb = b3 + (size_t)batch * CCH * P3;
        db = d3 + (size_t)batch * P3 * CCH;
    } else {
        pt -= T3TILES;
        P  = P2;
        ab = a2 + (size_t)batch * CCH * P2;
        bb = b2 + (size_t)batch * CCH * P2;
        db = d2 + (size_t)batch * P2 * CCH;
    }

    const int p0 = pt * 32, c0 = ct * 32;
    const int tx = threadIdx.x, ty = threadIdx.y;   // 32 x 8

    #pragma unroll
    for (int i = 0; i < 32; i += 8) {
        int c = c0 + ty + i;
        int p = p0 + tx;
        if (c < CCH)
            tile[ty + i][tx] = ab[(size_t)c * P + p] + bb[(size_t)c * P + p];
    }
    __syncthreads();
    #pragma unroll
    for (int i = 0; i < 32; i += 8) {
        int p = p0 + ty + i;
        int c = c0 + tx;
        if (c < CCH)
            db[(size_t)p * CCH + c] = __float2half_rn(tile[tx][ty + i]);
    }
}

// ---------------- pass 2: warp-per-voxel gather (fp16 taps, fp32 accum) ----
// block = 256 threads = 8 warps = 8 consecutive z of one (b,x,y) column
__global__ void __launch_bounds__(256) sample_kernel(const float* __restrict__ pp,
                                                     float* __restrict__ out)
{
    __shared__ float sm[8][204];     // rows 16B-aligned (816B)

    const int bid  = blockIdx.x;
    const int zc   = bid & 7;        // z chunk (8 per column)
    int rest       = bid >> 3;
    const int y    = rest % YDIM; rest /= YDIM;
    const int x    = rest % XDIM;
    const int b    = rest / XDIM;

    const int warp = threadIdx.x >> 5;
    const int lane = threadIdx.x & 31;
    const int z    = zc * 8 + warp;

    if (z < ZDIM) {
        // voxel index in projected_pix order: v = x*(Z*Y) + z*Y + y
        const int v = x * (ZDIM * YDIM) + z * YDIM + y;
        const float* g = pp + ((size_t)b * NVOX + v) * 3;
        const float px = __ldg(g + 0), py = __ldg(g + 1), pz = __ldg(g + 2);

        // ---- 3D taps ----
        const float gx3 = (px + 1.f) * 0.5f * (W3 - 1);
        const float gy3 = (py + 1.f) * 0.5f * (H3 - 1);
        const float gz3 = (pz + 1.f) * 0.5f * (D3 - 1);
        const float fx3 = floorf(gx3), fy3 = floorf(gy3), fz3 = floorf(gz3);
        const int ix3 = (int)fx3, iy3 = (int)fy3, iz3 = (int)fz3;
        const float wx3 = gx3 - fx3, wy3 = gy3 - fy3, wz3 = gz3 - fz3;

        int   off3[8];
        float w3[8];
        #pragma unroll
        for (int t = 0; t < 8; t++) {
            const int dx = t & 1, dy = (t >> 1) & 1, dz = (t >> 2) & 1;
            const int xi = ix3 + dx, yi = iy3 + dy, zi = iz3 + dz;
            const bool valid = (xi >= 0) & (xi < W3) & (yi >= 0) & (yi < H3) &
                               (zi >= 0) & (zi < D3);
            const int xcl = min(max(xi, 0), W3 - 1);
            const int ycl = min(max(yi, 0), H3 - 1);
            const int zcl = min(max(zi, 0), D3 - 1);
            off3[t] = (zcl * H3 + ycl) * W3 + xcl;
            float w = (dx ? wx3 : 1.f - wx3) * (dy ? wy3 : 1.f - wy3) *
                      (dz ? wz3 : 1.f - wz3);
            w3[t] = valid ? w : 0.f;
        }

        // ---- 2D taps ----
        const float gx2 = (px + 1.f) * 0.5f * (W2 - 1);
        const float gy2 = (py + 1.f) * 0.5f * (H2 - 1);
        const float fx2 = floorf(gx2), fy2 = floorf(gy2);
        const int ix2 = (int)fx2, iy2 = (int)fy2;
        const float wx2 = gx2 - fx2, wy2 = gy2 - fy2;

        int   off2[4];
        float w2[4];
        #pragma unroll
        for (int t = 0; t < 4; t++) {
            const int dx = t & 1, dy = (t >> 1) & 1;
            const int xi = ix2 + dx, yi = iy2 + dy;
            const bool valid = (xi >= 0) & (xi < W2) & (yi >= 0) & (yi < H2);
            const int xcl = min(max(xi, 0), W2 - 1);
            const int ycl = min(max(yi, 0), H2 - 1);
            off2[t] = ycl * W2 + xcl;
            float w = (dx ? wx2 : 1.f - wx2) * (dy ? wy2 : 1.f - wy2);
            w2[t] = valid ? w : 0.f;
        }

        // ---- channel accumulation: half8 (uint4) loads, fp32 accum ----
        const uint4* s3 = (const uint4*)g_s3 + (size_t)b * P3 * NC8;
        const uint4* s2 = (const uint4*)g_s2 + (size_t)b * P2 * NC8;

        const int cc = lane;            // 0..24 active
        if (cc < NC8) {
            float ax = 0.f, ay = 0.f, az = 0.f, aw = 0.f;
            float bx = 0.f, by = 0.f, bz = 0.f, bw = 0.f;
            #pragma unroll
            for (int t = 0; t < 8; t++) {
                const uint4 vv = s3[(size_t)off3[t] * NC8 + cc];
                const __half2* h = (const __half2*)&vv;
                const float2 f0 = __half22float2(h[0]);
                const float2 f1 = __half22float2(h[1]);
                const float2 f2 = __half22float2(h[2]);
                const float2 f3 = __half22float2(h[3]);
                const float w = w3[t];
                ax += w * f0.x; ay += w * f0.y;
                az += w * f1.x; aw += w * f1.y;
                bx += w * f2.x; by += w * f2.y;
                bz += w * f3.x; bw += w * f3.y;
            }
            #pragma unroll
            for (int t = 0; t < 4; t++) {
                const uint4 vv = s2[(size_t)off2[t] * NC8 + cc];
                const __half2* h = (const __half2*)&vv;
                const float2 f0 = __half22float2(h[0]);
                const float2 f1 = __half22float2(h[1]);
                const float2 f2 = __half22float2(h[2]);
                const float2 f3 = __half22float2(h[3]);
                const float w = w2[t];
                ax += w * f0.x; ay += w * f0.y;
                az += w * f1.x; aw += w * f1.y;
                bx += w * f2.x; by += w * f2.y;
                bz += w * f3.x; bw += w * f3.y;
            }
            *(float4*)&sm[warp][cc * 8]     = make_float4(ax, ay, az, aw);
            *(float4*)&sm[warp][cc * 8 + 4] = make_float4(bx, by, bz, bw);
        }
    }
    __syncthreads();

    // ---- cooperative coalesced write-out (streaming stores, evict-first) --
    const int z0 = zc * 8;
    float* ob = out + (size_t)b * CCH * NVOX +
                ((size_t)x * YDIM + y) * ZDIM + z0;
    #pragma unroll
    for (int idx = threadIdx.x; idx < CCH * 4; idx += 256) {
        const int c  = idx >> 2;
        const int zp = idx & 3;
        if (z0 + 2 * zp < ZDIM) {
            float2 v = make_float2(sm[2 * zp][c], sm[2 * zp + 1][c]);
            __stcs((float2*)(ob + (size_t)c * NVOX + 2 * zp), v);
        }
    }
}

// ---------------- launch ----------------
extern "C" void kernel_launch(void* const* d_in, const int* in_sizes, int n_in,
                              void* d_out, int out_size)
{
    const float* x3a = (const float*)d_in[0];
    const float* x3b = (const float*)d_in[1];
    const float* x2a = (const float*)d_in[2];
    const float* x2b = (const float*)d_in[3];
    const float* pp  = (const float*)d_in[4];
    float* out = (float*)d_out;

    __half* s3ptr = nullptr;
    __half* s2ptr = nullptr;
    cudaGetSymbolAddress((void**)&s3ptr, g_s3);
    cudaGetSymbolAddress((void**)&s2ptr, g_s2);

    // pass 1: fused fold + transpose (3D + 2D in one launch)
    {
        dim3 blk(32, 8);
        dim3 grd(T3TILES + T2TILES, (CCH + 31) / 32, NB);  // 3000 x 7 x 2
        transpose_add_kernel<<<grd, blk>>>(x3a, x3b, x2a, x2b, s3ptr, s2ptr);
    }

    // pass 2: warp-per-voxel sampling with staged streaming stores
    {
        const int nblocks = NB * XDIM * YDIM * 8;  // 34560
        sample_kernel<<<nblocks, 256>>>(pp, out);
    }
}

// round 7
// speedup vs baseline: 2.3632x; 1.0965x over previous
#include <cuda_runtime.h>
#include <cuda_fp16.h>
#include <cstdint>

// ---------------- problem constants ----------------
#define CCH   200               // channels
#define NC8   25                // CCH/8 half8 (uint4) chunks
#define D3    16
#define H3    60
#define W3    80
#define P3    (D3*H3*W3)        // 76800 positions per batch (3D)
#define H2    120
#define W2    160
#define P2    (H2*W2)           // 19200 positions per batch (2D)
#define XDIM  60
#define YDIM  36
#define ZDIM  60
#define NVOX  (XDIM*YDIM*ZDIM)  // 129600
#define NB    2
#define VPB   10                // voxels (z) per block
#define ZCH   (ZDIM/VPB)        // 6 z-chunks per column

#define T3TILES (P3/32)         // 2400
#define T2TILES (P2/32)         // 600

// channel-last fp16 scratch: s3[b][pos][c], s2[b][pos][c]
__device__ __align__(16) __half g_s3[NB * P3 * CCH];   // 61.4 MB
__device__ __align__(16) __half g_s2[NB * P2 * CCH];   // 15.4 MB

// ---------------- pass 1: fused add + transpose (C,P)->(P,C), fp32->fp16 ---
__global__ void transpose_add_kernel(const float* __restrict__ a3,
                                     const float* __restrict__ b3,
                                     const float* __restrict__ a2,
                                     const float* __restrict__ b2,
                                     __half* __restrict__ d3,
                                     __half* __restrict__ d2)
{
    __shared__ float tile[32][33];
    int pt = blockIdx.x;
    const int ct = blockIdx.y;
    const int batch = blockIdx.z;

    const float *ab, *bb;
    __half* db;
    int P;
    if (pt < T3TILES) {
        P  = P3;
        ab = a3 + (size_t)batch * CCH * P3;
        bb = b3 + (size_t)batch * CCH * P3;
        db = d3 + (size_t)batch * P3 * CCH;
    } else {
        pt -= T3TILES;
        P  = P2;
        ab = a2 + (size_t)batch * CCH * P2;
        bb = b2 + (size_t)batch * CCH * P2;
        db = d2 + (size_t)batch * P2 * CCH;
    }

    const int p0 = pt * 32, c0 = ct * 32;
    const int tx = threadIdx.x, ty = threadIdx.y;   // 32 x 8

    #pragma unroll
    for (int i = 0; i < 32; i += 8) {
        int c = c0 + ty + i;
        int p = p0 + tx;
        if (c < CCH)
            tile[ty + i][tx] = ab[(size_t)c * P + p] + bb[(size_t)c * P + p];
    }
    __syncthreads();
    #pragma unroll
    for (int i = 0; i < 32; i += 8) {
        int p = p0 + ty + i;
        int c = c0 + tx;
        if (c < CCH)
            db[(size_t)p * CCH + c] = __float2half_rn(tile[tx][ty + i]);
    }
}

// ---------------- pass 2: 10 voxels per 256-thread block ----------------
// Phase A: 120 threads compute one (voxel,tap) each -> smem
// Phase B: 250 threads = (voxel q, chunk cc) gather + stage
// Phase C: coalesced write-out
__global__ void __launch_bounds__(256) sample_kernel(const float* __restrict__ pp,
                                                     float* __restrict__ out)
{
    __shared__ int   sm_off[VPB][12];    // uint4-index incl. batch base
    __shared__ float sm_w[VPB][12];
    __shared__ float st[VPB][204];       // staged results

    const int bid = blockIdx.x;
    const int zc  = bid % ZCH;
    int rest      = bid / ZCH;
    const int y   = rest % YDIM; rest /= YDIM;
    const int x   = rest % XDIM;
    const int b   = rest / XDIM;
    const int z0  = zc * VPB;
    const int tid = threadIdx.x;

    // ---------- Phase A: tap setup ----------
    if (tid < VPB * 12) {
        const int q = tid / 12;          // voxel in block
        const int t = tid % 12;          // tap id: 0..7 = 3D, 8..11 = 2D
        const int z = z0 + q;
        const int v = x * (ZDIM * YDIM) + z * YDIM + y;
        const float* g = pp + ((size_t)b * NVOX + v) * 3;
        const float px = __ldg(g + 0), py = __ldg(g + 1);

        int offset; float weight;
        if (t < 8) {
            const float pz = __ldg(g + 2);
            const float gx = (px + 1.f) * 0.5f * (W3 - 1);
            const float gy = (py + 1.f) * 0.5f * (H3 - 1);
            const float gz = (pz + 1.f) * 0.5f * (D3 - 1);
            const float fx = floorf(gx), fy = floorf(gy), fz = floorf(gz);
            const float wx = gx - fx, wy = gy - fy, wz = gz - fz;
            const int dx = t & 1, dy = (t >> 1) & 1, dz = (t >> 2) & 1;
            const int xi = (int)fx + dx, yi = (int)fy + dy, zi = (int)fz + dz;
            const bool valid = (xi >= 0) & (xi < W3) & (yi >= 0) & (yi < H3) &
                               (zi >= 0) & (zi < D3);
            const int xc = min(max(xi, 0), W3 - 1);
            const int yc = min(max(yi, 0), H3 - 1);
            const int zcv = min(max(zi, 0), D3 - 1);
            const int pos = (zcv * H3 + yc) * W3 + xc;
            offset = b * (P3 * NC8) + pos * NC8;
            float w = (dx ? wx : 1.f - wx) * (dy ? wy : 1.f - wy) *
                      (dz ? wz : 1.f - wz);
            weight = valid ? w : 0.f;
        } else {
            const float gx = (px + 1.f) * 0.5f * (W2 - 1);
            const float gy = (py + 1.f) * 0.5f * (H2 - 1);
            const float fx = floorf(gx), fy = floorf(gy);
            const float wx = gx - fx, wy = gy - fy;
            const int tt = t - 8;
            const int dx = tt & 1, dy = (tt >> 1) & 1;
            const int xi = (int)fx + dx, yi = (int)fy + dy;
            const bool valid = (xi >= 0) & (xi < W2) & (yi >= 0) & (yi < H2);
            const int xc = min(max(xi, 0), W2 - 1);
            const int yc = min(max(yi, 0), H2 - 1);
            const int pos = yc * W2 + xc;
            offset = b * (P2 * NC8) + pos * NC8;
            float w = (dx ? wx : 1.f - wx) * (dy ? wy : 1.f - wy);
            weight = valid ? w : 0.f;
        }
        sm_off[tid / 12][t] = offset;
        sm_w[tid / 12][t]   = weight;
    }
    __syncthreads();

    // ---------- Phase B: gather (fp16 taps, fp32 accum) ----------
    if (tid < VPB * NC8) {               // 250 active
        const int q  = tid / NC8;
        const int cc = tid % NC8;
        const uint4* s3 = (const uint4*)g_s3;
        const uint4* s2 = (const uint4*)g_s2;

        float ax = 0.f, ay = 0.f, az = 0.f, aw = 0.f;
        float bx = 0.f, by = 0.f, bz = 0.f, bw = 0.f;
        #pragma unroll
        for (int t = 0; t < 12; t++) {
            const uint4 vv = (t < 8) ? s3[sm_off[q][t] + cc]
                                     : s2[sm_off[q][t] + cc];
            const float w = sm_w[q][t];
            const __half2* h = (const __half2*)&vv;
            const float2 f0 = __half22float2(h[0]);
            const float2 f1 = __half22float2(h[1]);
            const float2 f2 = __half22float2(h[2]);
            const float2 f3 = __half22float2(h[3]);
            ax += w * f0.x; ay += w * f0.y;
            az += w * f1.x; aw += w * f1.y;
            bx += w * f2.x; by += w * f2.y;
            bz += w * f3.x; bw += w * f3.y;
        }
        *(float4*)&st[q][cc * 8]     = make_float4(ax, ay, az, aw);
        *(float4*)&st[q][cc * 8 + 4] = make_float4(bx, by, bz, bw);
    }
    __syncthreads();

    // ---------- Phase C: coalesced write-out: out[b][c][x][y][z] ----------
    float* ob = out + (size_t)b * CCH * NVOX +
                ((size_t)x * YDIM + y) * ZDIM + z0;
    // 1000 float2 items: c-major so each warp touches few sectors per c
    for (int idx = tid; idx < CCH * (VPB / 2); idx += 256) {
        const int c  = idx / (VPB / 2);
        const int zp = idx % (VPB / 2);
        float2 v = make_float2(st[2 * zp][c], st[2 * zp + 1][c]);
        __stcs((float2*)(ob + (size_t)c * NVOX + 2 * zp), v);
    }
}

// ---------------- launch ----------------
extern "C" void kernel_launch(void* const* d_in, const int* in_sizes, int n_in,
                              void* d_out, int out_size)
{
    const float* x3a = (const float*)d_in[0];
    const float* x3b = (const float*)d_in[1];
    const float* x2a = (const float*)d_in[2];
    const float* x2b = (const float*)d_in[3];
    const float* pp  = (const float*)d_in[4];
    float* out = (float*)d_out;

    __half* s3ptr = nullptr;
    __half* s2ptr = nullptr;
    cudaGetSymbolAddress((void**)&s3ptr, g_s3);
    cudaGetSymbolAddress((void**)&s2ptr, g_s2);

    // pass 1: fused fold + transpose (3D + 2D in one launch)
    {
        dim3 blk(32, 8);
        dim3 grd(T3TILES + T2TILES, (CCH + 31) / 32, NB);  // 3000 x 7 x 2
        transpose_add_kernel<<<grd, blk>>>(x3a, x3b, x2a, x2b, s3ptr, s2ptr);
    }

    // pass 2: 10-voxel blocks
    {
        const int nblocks = NB * XDIM * YDIM * ZCH;  // 25920
        sample_kernel<<<nblocks, 256>>>(pp, out);
    }
}